// round 6
// baseline (speedup 1.0000x reference)
#include <cuda_runtime.h>
#include <cstdint>
#include <cstddef>

// ---------------------------------------------------------------------------
// NonLocalBlock: B=16, C=64, H=W=64, C1=8, C2=32
// out = gamma * conv1x1(attn_out, w_last, b_last) + x
// Split-K attention: 2 key-halves per query tile -> 2 CTAs/SM occupancy.
// ---------------------------------------------------------------------------

#define DINL __device__ __forceinline__

DINL unsigned long long pk2(float lo, float hi) {
    unsigned long long r;
    asm("mov.b64 %0, {%1, %2};" : "=l"(r) : "f"(lo), "f"(hi));
    return r;
}
DINL void upk2(unsigned long long v, float& lo, float& hi) {
    asm("mov.b64 {%0, %1}, %2;" : "=f"(lo), "=f"(hi) : "l"(v));
}
DINL unsigned long long fma2(unsigned long long a, unsigned long long b, unsigned long long c) {
    unsigned long long d;
    asm("fma.rn.f32x2 %0, %1, %2, %3;" : "=l"(d) : "l"(a), "l"(b), "l"(c));
    return d;
}
DINL unsigned long long mul2(unsigned long long a, unsigned long long b) {
    unsigned long long d;
    asm("mul.rn.f32x2 %0, %1, %2;" : "=l"(d) : "l"(a), "l"(b));
    return d;
}
DINL unsigned long long add2(unsigned long long a, unsigned long long b) {
    unsigned long long d;
    asm("add.rn.f32x2 %0, %1, %2;" : "=l"(d) : "l"(a), "l"(b));
    return d;
}
DINL float ex2(float x) {
    float r;
    asm("ex2.approx.f32 %0, %1;" : "=f"(r) : "f"(x));
    return r;
}

// scratch (no allocation allowed -> __device__ globals)
__device__ float g_delta[16 * 4096 * 8];        // [b][n][8]
__device__ float g_phiP [16 * 8 * 1024];        // [b][c1][1024]
__device__ float g_gP   [16 * 1024 * 32];       // [b][m][32]
__device__ float g_pacc [16 * 2 * 4096 * 32];   // [b][half][q][32] partial PV
__device__ float g_pl   [16 * 2 * 4096];        // [b][half][q]     partial sum-exp

// ---------------------------------------------------------------------------
// Kernel 1: fused 3x conv1x1 (48 out ch) + 2x2 maxpool for phi/g.
// One thread per 2x1 pixel column; thread pairs merge pooling via shfl_xor(1).
// grid (8,16), 256 threads -> 128 CTAs.
// ---------------------------------------------------------------------------
__global__ __launch_bounds__(256, 1) void conv_pool_kernel(
    const float* __restrict__ x,
    const float* __restrict__ w_delta, const float* __restrict__ b_delta,
    const float* __restrict__ w_phi,   const float* __restrict__ b_phi,
    const float* __restrict__ w_g,     const float* __restrict__ b_g)
{
    __shared__ ulonglong2 ws[64][12];
    __shared__ float bias[48];
    const int tid = threadIdx.x;

    for (int i = tid; i < 3072; i += 256) {
        int c = i / 48, o = i - c * 48;
        float w;
        if (o < 8)       w = w_delta[o * 64 + c];
        else if (o < 16) w = w_phi[(o - 8) * 64 + c];
        else             w = w_g[(o - 16) * 64 + c];
        ((float*)&ws[c][0])[o] = w;
    }
    if (tid < 48)
        bias[tid] = (tid < 8) ? b_delta[tid] : (tid < 16) ? b_phi[tid - 8] : b_g[tid - 16];
    __syncthreads();

    const int b   = blockIdx.y;
    const int t   = blockIdx.x * 256 + tid;
    const int q   = t >> 1;
    const int col = t & 1;
    const int qy  = q >> 5, qx = q & 31;
    const int xcol = 2 * qx + col;
    const int row0 = 2 * qy;

    const float* xp = x + (size_t)b * 262144 + row0 * 64 + xcol;

    unsigned long long a0[24], a1[24];
#pragma unroll
    for (int k = 0; k < 24; k++) { a0[k] = 0ull; a1[k] = 0ull; }

#pragma unroll 4
    for (int c = 0; c < 64; c++) {
        float xv0 = xp[c * 4096];
        float xv1 = xp[c * 4096 + 64];
        unsigned long long x0 = pk2(xv0, xv0);
        unsigned long long x1 = pk2(xv1, xv1);
#pragma unroll
        for (int k = 0; k < 12; k++) {
            ulonglong2 w = ws[c][k];
            a0[2*k]   = fma2(w.x, x0, a0[2*k]);
            a0[2*k+1] = fma2(w.y, x0, a0[2*k+1]);
            a1[2*k]   = fma2(w.x, x1, a1[2*k]);
            a1[2*k+1] = fma2(w.y, x1, a1[2*k+1]);
        }
    }

    float f0[48], f1[48];
#pragma unroll
    for (int k = 0; k < 24; k++) {
        upk2(a0[k], f0[2*k], f0[2*k+1]);
        upk2(a1[k], f1[2*k], f1[2*k+1]);
    }

    float* dp0 = g_delta + ((size_t)(b * 4096 + row0 * 64 + xcol)) * 8;
#pragma unroll
    for (int j = 0; j < 8; j++) {
        dp0[j]          = f0[j] + bias[j];
        dp0[64 * 8 + j] = f1[j] + bias[j];
    }

    float pm[40];
#pragma unroll
    for (int j = 0; j < 40; j++) {
        float v = fmaxf(f0[8 + j], f1[8 + j]);
        pm[j] = fmaxf(v, __shfl_xor_sync(0xffffffffu, v, 1));
    }
    float* gp = g_gP + ((size_t)(b * 1024 + q)) * 32;
    if (col == 0) {
#pragma unroll
        for (int j = 0; j < 8; j++)
            g_phiP[(b * 8 + j) * 1024 + q] = pm[j] + bias[8 + j];
#pragma unroll
        for (int j = 0; j < 16; j++)
            gp[j] = pm[8 + j] + bias[16 + j];
    } else {
#pragma unroll
        for (int j = 16; j < 32; j++)
            gp[j] = pm[8 + j] + bias[16 + j];
    }
}

// ---------------------------------------------------------------------------
// Kernel 2a: attention partials over one key-half (512 keys).
// grid (16,16): x = qtile(8) | half(1)<<3 ... actually x in [0,16): low 3 bits
// qtile, bit 3 half. 256 threads, 2 q/thread. smem 80 KB -> 2 CTAs/SM.
// ---------------------------------------------------------------------------
__global__ __launch_bounds__(256, 2) void attn_partial_kernel()
{
    extern __shared__ float sm[];
    float* Vsm = sm;              // 512*32 = 16384 floats (64 KB)
    float* Ksm = sm + 16384;      // 512*8  =  4096 floats (16 KB)

    const int tid  = threadIdx.x;
    const int b    = blockIdx.y;
    const int qt   = blockIdx.x & 7;
    const int half = blockIdx.x >> 3;
    const int m0   = half * 512;

    {   // V half: straight copy
        const float4* src = (const float4*)(g_gP + ((size_t)b * 1024 + m0) * 32);
        float4* dst = (float4*)Vsm;
        for (int i = tid; i < 4096; i += 256) dst[i] = src[i];
    }
    // K gather (reference batch-mix): K[b][j][m] = phiP[(b*8+j)%16][(b*8+j)/16][m]
#pragma unroll
    for (int j = 0; j < 8; j++) {
        int idx = b * 8 + j;
        const float* src = g_phiP + (size_t)((idx & 15) * 8 + (idx >> 4)) * 1024 + m0;
        for (int m = tid; m < 512; m += 256) Ksm[m * 8 + j] = src[m];
    }
    __syncthreads();

    const int q0 = qt * 512 + tid;
    const int q1 = q0 + 256;
    const ulonglong2* dq0 = (const ulonglong2*)(g_delta + ((size_t)b * 4096 + q0) * 8);
    const ulonglong2* dq1 = (const ulonglong2*)(g_delta + ((size_t)b * 4096 + q1) * 8);
    const unsigned long long L2E = pk2(1.4426950408889634f, 1.4426950408889634f);
    ulonglong2 qa, qb, qc, qd;
    { ulonglong2 r0 = dq0[0], r1 = dq0[1], r2 = dq1[0], r3 = dq1[1];
      qa.x = mul2(r0.x, L2E); qa.y = mul2(r0.y, L2E);
      qb.x = mul2(r1.x, L2E); qb.y = mul2(r1.y, L2E);
      qc.x = mul2(r2.x, L2E); qc.y = mul2(r2.y, L2E);
      qd.x = mul2(r3.x, L2E); qd.y = mul2(r3.y, L2E); }

    unsigned long long acc0[16], acc1[16];
#pragma unroll
    for (int k = 0; k < 16; k++) { acc0[k] = 0ull; acc1[k] = 0ull; }
    float l0 = 0.f, l1 = 0.f;

    for (int mb = 0; mb < 512; mb += 8) {
        const ulonglong2* Kp = (const ulonglong2*)Ksm + 2 * mb;
        const ulonglong2* Vp = (const ulonglong2*)Vsm + 8 * mb;

        float e0[8], e1[8];
#pragma unroll
        for (int u = 0; u < 8; u++) {
            ulonglong2 kA = Kp[2 * u], kB = Kp[2 * u + 1];
            unsigned long long p0 = mul2(qa.x, kA.x);
            p0 = fma2(qa.y, kA.y, p0);
            p0 = fma2(qb.x, kB.x, p0);
            p0 = fma2(qb.y, kB.y, p0);
            unsigned long long p1 = mul2(qc.x, kA.x);
            p1 = fma2(qc.y, kA.y, p1);
            p1 = fma2(qd.x, kB.x, p1);
            p1 = fma2(qd.y, kB.y, p1);
            float s0a, s0b, s1a, s1b;
            upk2(p0, s0a, s0b);
            upk2(p1, s1a, s1b);
            e0[u] = ex2(s0a + s0b);
            e1[u] = ex2(s1a + s1b);
        }
#pragma unroll
        for (int u = 0; u < 8; u++) {
            unsigned long long e0p = pk2(e0[u], e0[u]);
            unsigned long long e1p = pk2(e1[u], e1[u]);
            l0 += e0[u];
            l1 += e1[u];
            const ulonglong2* v = Vp + 8 * u;
#pragma unroll
            for (int t = 0; t < 8; t++) {
                ulonglong2 vv = v[t];
                acc0[2*t]   = fma2(e0p, vv.x, acc0[2*t]);
                acc0[2*t+1] = fma2(e0p, vv.y, acc0[2*t+1]);
                acc1[2*t]   = fma2(e1p, vv.x, acc1[2*t]);
                acc1[2*t+1] = fma2(e1p, vv.y, acc1[2*t+1]);
            }
        }
    }

    // write partials: acc0[k] holds channels (2k,2k+1) -> contiguous 32 floats
    ulonglong2* pa0 = (ulonglong2*)(g_pacc + ((size_t)((b * 2 + half) * 4096 + q0)) * 32);
    ulonglong2* pa1 = (ulonglong2*)(g_pacc + ((size_t)((b * 2 + half) * 4096 + q1)) * 32);
#pragma unroll
    for (int t = 0; t < 8; t++) {
        ulonglong2 w0; w0.x = acc0[2*t]; w0.y = acc0[2*t+1];
        ulonglong2 w1; w1.x = acc1[2*t]; w1.y = acc1[2*t+1];
        pa0[t] = w0;
        pa1[t] = w1;
    }
    g_pl[(size_t)(b * 2 + half) * 4096 + q0] = l0;
    g_pl[(size_t)(b * 2 + half) * 4096 + q1] = l1;
}

// ---------------------------------------------------------------------------
// Kernel 2b: combine halves + fused final conv + residual.
// grid (8,16), 256 threads, 2 q/thread.
// ---------------------------------------------------------------------------
__global__ __launch_bounds__(256, 1) void combine_kernel(
    const float* __restrict__ x,
    const float* __restrict__ w_last, const float* __restrict__ b_last,
    const float* __restrict__ gamma,  float* __restrict__ out)
{
    __shared__ float wl[2048];
    __shared__ float bl[64];
    const int tid = threadIdx.x;
    const int b   = blockIdx.y;

    for (int i = tid; i < 2048; i += 256) wl[i] = w_last[i];
    if (tid < 64) bl[tid] = b_last[tid];
    __syncthreads();

    const int q0 = blockIdx.x * 512 + tid;
    const int q1 = q0 + 256;

    const ulonglong2* pa00 = (const ulonglong2*)(g_pacc + ((size_t)((b * 2 + 0) * 4096 + q0)) * 32);
    const ulonglong2* pa10 = (const ulonglong2*)(g_pacc + ((size_t)((b * 2 + 1) * 4096 + q0)) * 32);
    const ulonglong2* pa01 = (const ulonglong2*)(g_pacc + ((size_t)((b * 2 + 0) * 4096 + q1)) * 32);
    const ulonglong2* pa11 = (const ulonglong2*)(g_pacc + ((size_t)((b * 2 + 1) * 4096 + q1)) * 32);

    unsigned long long acc0[16], acc1[16];
#pragma unroll
    for (int t = 0; t < 8; t++) {
        ulonglong2 u0 = pa00[t], v0 = pa10[t];
        ulonglong2 u1 = pa01[t], v1 = pa11[t];
        acc0[2*t]   = add2(u0.x, v0.x);
        acc0[2*t+1] = add2(u0.y, v0.y);
        acc1[2*t]   = add2(u1.x, v1.x);
        acc1[2*t+1] = add2(u1.y, v1.y);
    }
    const float l0 = g_pl[(size_t)(b * 2) * 4096 + q0] + g_pl[(size_t)(b * 2 + 1) * 4096 + q0];
    const float l1 = g_pl[(size_t)(b * 2) * 4096 + q1] + g_pl[(size_t)(b * 2 + 1) * 4096 + q1];

    const float gm  = gamma[0];
    const float gi0 = __fdividef(gm, l0);
    const float gi1 = __fdividef(gm, l1);
    const float* xb = x   + (size_t)b * 262144;
    float*       ob = out + (size_t)b * 262144;
    const ulonglong2* wl2 = (const ulonglong2*)wl;

    for (int c = 0; c < 64; c++) {
        const ulonglong2* wr = wl2 + c * 8;
        ulonglong2 w0 = wr[0];
        unsigned long long s0 = mul2(acc0[0], w0.x);
        unsigned long long s1 = mul2(acc1[0], w0.x);
        s0 = fma2(acc0[1], w0.y, s0);
        s1 = fma2(acc1[1], w0.y, s1);
#pragma unroll
        for (int t = 1; t < 8; t++) {
            ulonglong2 w = wr[t];
            s0 = fma2(acc0[2*t],   w.x, s0);
            s1 = fma2(acc1[2*t],   w.x, s1);
            s0 = fma2(acc0[2*t+1], w.y, s0);
            s1 = fma2(acc1[2*t+1], w.y, s1);
        }
        float r0a, r0b, r1a, r1b;
        upk2(s0, r0a, r0b);
        upk2(s1, r1a, r1b);
        float base = gm * bl[c];
        ob[c * 4096 + q0] = fmaf(gi0, r0a + r0b, base + xb[c * 4096 + q0]);
        ob[c * 4096 + q1] = fmaf(gi1, r1a + r1b, base + xb[c * 4096 + q1]);
    }
}

// ---------------------------------------------------------------------------
extern "C" void kernel_launch(void* const* d_in, const int* in_sizes, int n_in,
                              void* d_out, int out_size)
{
    const float* x  = (const float*)d_in[0];
    const float* wd = (const float*)d_in[1];
    const float* bd = (const float*)d_in[2];
    const float* wp = (const float*)d_in[3];
    const float* bp = (const float*)d_in[4];
    const float* wg = (const float*)d_in[5];
    const float* bg = (const float*)d_in[6];
    const float* wl = (const float*)d_in[7];
    const float* bl = (const float*)d_in[8];
    const float* gm = (const float*)d_in[9];

    conv_pool_kernel<<<dim3(8, 16), 256>>>(x, wd, bd, wp, bp, wg, bg);

    const int shm = (16384 + 4096) * 4;  // 81920 B -> 2 CTAs/SM
    cudaFuncSetAttribute(attn_partial_kernel, cudaFuncAttributeMaxDynamicSharedMemorySize, shm);
    attn_partial_kernel<<<dim3(16, 16), 256, shm>>>();

    combine_kernel<<<dim3(8, 16), 256>>>(x, wl, bl, gm, (float*)d_out);
}